// round 15
// baseline (speedup 1.0000x reference)
#include <cuda_runtime.h>
#include <cstdint>

// SCM_19061064860184 — R15: wide-halo cluster scan (halo 48, epoch every 24 ticks).
// R14 with the stage-store alignment trap fixed: SW=258 rows are only 8B-aligned
// on odd rows, so stage writes are 2x float2 (not float4). g_R/g_scr align(16).
// Per batch: 4-CTA cluster x 256 threads. Warp owns 32 positions, computes a
// 128-wide window redundantly (4 slots/thread, two f32x2 pipelines).
// 42 cluster barriers instead of 128. PHASE-0 form: s_t = convS(s_{t-1}) + R[t].

#define NN 1024
#define TT 1024
#define NTH 256
#define CLC 4
#define OWNC 256
#define EXW2 352          // CTA exchange window: 256 own + 2*48 halo
#define SW 258            // stage row stride (258 % 32 == 2 -> conflict-free flush)
#define FULLM 0xffffffffu

struct alignas(16) Smem {
    float sEx[2][EXW2];
    float uEx[2][EXW2];
    float stage[32][SW];
};

__device__ __align__(16) float g_scr[8 * NN * TT];          // phase-A output
__device__ __align__(16) float g_R[8 * NN * TT + 4 * NN];   // precomputed R (+4 pad rows)

// ---------- packed f32x2 helpers ----------
__device__ __forceinline__ uint64_t pk2(float lo, float hi) {
    uint64_t r; asm("mov.b64 %0, {%1, %2};" : "=l"(r) : "f"(lo), "f"(hi)); return r;
}
__device__ __forceinline__ void upk2(uint64_t v, float& lo, float& hi) {
    asm("mov.b64 {%0, %1}, %2;" : "=f"(lo), "=f"(hi) : "l"(v));
}
__device__ __forceinline__ uint64_t fma2(uint64_t a, uint64_t b, uint64_t c) {
    uint64_t d; asm("fma.rn.f32x2 %0, %1, %2, %3;" : "=l"(d) : "l"(a), "l"(b), "l"(c)); return d;
}
__device__ __forceinline__ uint64_t add2(uint64_t a, uint64_t b) {
    uint64_t d; asm("add.rn.f32x2 %0, %1, %2;" : "=l"(d) : "l"(a), "l"(b)); return d;
}

// scalar 4-slot conv (same per-output tap order as packed path)
__device__ __forceinline__ void conv4acc(float o[4],
    float L2, float L1, float v0, float v1, float v2, float v3, float R0, float R1,
    const float tp[5])
{
    o[0] = fmaf(tp[0], L2, o[0]); o[0] = fmaf(tp[1], L1, o[0]); o[0] = fmaf(tp[2], v0, o[0]);
    o[0] = fmaf(tp[3], v1, o[0]); o[0] = fmaf(tp[4], v2, o[0]);
    o[1] = fmaf(tp[0], L1, o[1]); o[1] = fmaf(tp[1], v0, o[1]); o[1] = fmaf(tp[2], v1, o[1]);
    o[1] = fmaf(tp[3], v2, o[1]); o[1] = fmaf(tp[4], v3, o[1]);
    o[2] = fmaf(tp[0], v0, o[2]); o[2] = fmaf(tp[1], v1, o[2]); o[2] = fmaf(tp[2], v2, o[2]);
    o[2] = fmaf(tp[3], v3, o[2]); o[2] = fmaf(tp[4], R0, o[2]);
    o[3] = fmaf(tp[0], v1, o[3]); o[3] = fmaf(tp[1], v2, o[3]); o[3] = fmaf(tp[2], v3, o[3]);
    o[3] = fmaf(tp[3], R0, o[3]); o[3] = fmaf(tp[4], R1, o[3]);
}

#define HALO4(v0, v1, v2, v3, L2, L1, R0, R1) do { \
    L1 = __shfl_up_sync(FULLM, v3, 1);             \
    L2 = __shfl_up_sync(FULLM, v2, 1);             \
    R0 = __shfl_down_sync(FULLM, v0, 1);           \
    R1 = __shfl_down_sync(FULLM, v1, 1);           \
} while (0)

#define CLUSTER_ARRIVE() asm volatile("barrier.cluster.arrive.aligned;" ::: "memory")
#define CLUSTER_WAIT()   asm volatile("barrier.cluster.wait.aligned;"   ::: "memory")

__device__ __forceinline__ void dsm_store2(const float* lptr, int trank, float a, float b)
{
    uint32_t la = (uint32_t)__cvta_generic_to_shared(lptr);
    uint32_t ra;
    asm volatile("mapa.shared::cluster.u32 %0, %1, %2;" : "=r"(ra) : "r"(la), "r"(trank));
    asm volatile("st.shared::cluster.v2.f32 [%0], {%1, %2};"
                 :: "r"(ra), "f"(a), "f"(b) : "memory");
}

// stage store: two float2s (stage rows are only 8B-aligned on odd rows)
__device__ __forceinline__ void stage_store4(float* p, float a, float b, float c, float d)
{
    *reinterpret_cast<float2*>(p)     = make_float2(a, b);
    *reinterpret_cast<float2*>(p + 2) = make_float2(c, d);
}

// warp-private flush of 16 u-rows (i0..i0+15, i0 % 16 == 0) for warp w's 32 own
// positions; transposed + reversed; float4 gmem stores (4 lanes share a 64B segment).
__device__ __forceinline__ void flushw(const float (*stg)[SW], float* __restrict__ O,
                                       int i0, int w, int lane, int rank)
{
    const int q = lane & 3;
    const int r = lane >> 2;
    const int cb = NN - 4 - i0 - 4 * q;
    #pragma unroll
    for (int k = 0; k < 4; ++k) {
        const int oi = r + 8 * k;                     // own index 0..31
        const int sa = w * 32 + oi;                   // stage column
        float4 v;
        v.x = stg[(i0 + 4 * q + 3) & 31][sa];
        v.y = stg[(i0 + 4 * q + 2) & 31][sa];
        v.z = stg[(i0 + 4 * q + 1) & 31][sa];
        v.w = stg[(i0 + 4 * q + 0) & 31][sa];
        *reinterpret_cast<float4*>(O + (size_t)(rank * OWNC + w * 32 + oi) * NN + cb) = v;
    }
}

// PHASE 0: writes g_scr; PHASE 1: writes OUTparam. R always g_R.
template <int COLTAPS, int PHASE>
__global__ void __launch_bounds__(NTH, 1) __cluster_dims__(CLC, 1, 1)
scan_kernel(float* __restrict__ OUTparam,
            const float* __restrict__ preBw, const float* __restrict__ preBb,
            const float* __restrict__ cAw,
            const float* __restrict__ cBw, const float* __restrict__ cBb)
{
    extern __shared__ char raw[];
    Smem* sm = reinterpret_cast<Smem*>(raw);
    const int rank  = blockIdx.x & (CLC - 1);
    const int batch = blockIdx.x >> 2;
    const float* RIN = g_R + (size_t)batch * NN * TT;
    float* O = (PHASE == 0 ? g_scr : OUTparam) + (size_t)batch * NN * TT;

    const int tid = threadIdx.x, w = tid >> 5, lane = tid & 31;
#define TI(k) (COLTAPS ? (5 * (k) + 2) : (10 + (k)))
    float aS[5], bS[5], bX[5], pB[5];
    uint64_t aSp[5], bSp[5], bXp[5];
    #pragma unroll
    for (int k = 0; k < 5; ++k) {
        aS[k] = cAw[TI(k)];
        bS[k] = cBw[TI(k)];
        bX[k] = cBw[25 + TI(k)];
        pB[k] = preBw[TI(k)];
        aSp[k] = pk2(aS[k], aS[k]);
        bSp[k] = pk2(bS[k], bS[k]);
        bXp[k] = pk2(bX[k], bX[k]);
    }
    const float bB = cBb[0], pBb = preBb[0];
    const uint64_t bBp = pk2(bB, bB);
    const uint64_t Z64 = pk2(0.f, 0.f);
#undef TI

    // geometry: global warp wg owns [wg*32, wg*32+32); window = own +/- 48.
    const int wg = rank * 8 + w;
    const int g0 = wg * 32 - 48 + 4 * lane;      // global coord of slot 0
    bool inD[4];
    #pragma unroll
    for (int j = 0; j < 4; ++j) inD[j] = (g0 + j >= 0) && (g0 + j < NN);
    const bool own = (lane >= 12 && lane < 20);
    const bool edgeW = (wg <= 1) || (wg >= 30);
    const int exIdx = w * 32 + 4 * lane;         // exchange-window index (own: w*32+48..+76)
    const int stIdx = exIdx - 48;                // CTA-local own index for stage (own lanes)
    const bool pubR = (rank < CLC - 1) && own && (exIdx >= 256);
    const bool pubL = (rank > 0) && own && (exIdx < 96);
    const int gr = g0 < 0 ? 0 : (g0 > NN - 4 ? NN - 4 : g0);   // float4-safe clamp
    const float (*stg)[SW] = sm->stage;

    // zero exchange buffers (domain-edge halo regions stay 0 = padding)
    {
        float* p0 = &sm->sEx[0][0];
        float* p1 = &sm->uEx[0][0];
        for (int i = tid; i < 2 * EXW2; i += NTH) { p0[i] = 0.f; p1[i] = 0.f; }
    }
    CLUSTER_ARRIVE();
    CLUSTER_WAIT();

    const int RS = NN;
    auto rowp = [&](int t) { return reinterpret_cast<const float4*>(RIN + (size_t)t * RS + gr); };
    float4 ra  = *rowp(0);
    float4 rb  = *rowp(1);
    float4 rr0 = *rowp(2);
    float4 rr1 = *rowp(3);
    float4 rr2 = *rowp(4);
    float4 rr3 = *rowp(5);

    float s0, s1, s2, s3, u0, u1, u2, u3;

    // t = 0: s_0 = R[0] masked
    s0 = inD[0] ? ra.x : 0.f;
    s1 = inD[1] ? ra.y : 0.f;
    s2 = inD[2] ? ra.z : 0.f;
    s3 = inD[3] ? ra.w : 0.f;

    // t = 1: s_1 = convS(s_0) + R[1] ; u_0 = preB(s_0)   (scalar path)
    {
        float L2, L1, R0, R1;
        HALO4(s0, s1, s2, s3, L2, L1, R0, R1);
        float a[4] = {rb.x, rb.y, rb.z, rb.w};
        conv4acc(a, L2, L1, s0, s1, s2, s3, R0, R1, aS);
        float c[4] = {pBb, pBb, pBb, pBb};
        conv4acc(c, L2, L1, s0, s1, s2, s3, R0, R1, pB);
        if (edgeW) {
            #pragma unroll
            for (int j = 0; j < 4; ++j) if (!inD[j]) { a[j] = 0.f; c[j] = 0.f; }
        }
        s0 = a[0]; s1 = a[1]; s2 = a[2]; s3 = a[3];
        u0 = c[0]; u1 = c[1]; u2 = c[2]; u3 = c[3];
        if (own)
            stage_store4(&sm->stage[0][stIdx], u0, u1, u2, u3);
    }

    int te = 24;     // first exchange tick (decay 2*24 = 48 = halo, exactly tight)
    int eb = 0;      // exchange buffer toggle

    auto body = [&](int t, float4& rc, const float4* ld) {
        float sL2, sL1, sR0, sR1, uL2, uL1, uR0, uR1;
        HALO4(s0, s1, s2, s3, sL2, sL1, sR0, sR1);
        HALO4(u0, u1, u2, u3, uL2, uL1, uR0, uR1);

        // packed shifted windows (7 unique per array)
        const uint64_t Ps0 = pk2(sL2, sL1), Ps1 = pk2(sL1, s0), Ps2 = pk2(s0, s1),
                       Ps3 = pk2(s1, s2),  Ps4 = pk2(s2, s3),
                       Qs3 = pk2(s3, sR0), Qs4 = pk2(sR0, sR1);
        const uint64_t Pu0 = pk2(uL2, uL1), Pu1 = pk2(uL1, u0), Pu2 = pk2(u0, u1),
                       Pu3 = pk2(u1, u2),  Pu4 = pk2(u2, u3),
                       Qu3 = pk2(u3, uR0), Qu4 = pk2(uR0, uR1);

        // s_t (two pipes), accumulator starts at R
        uint64_t A0 = pk2(rc.x, rc.y);
        A0 = fma2(aSp[0], Ps0, A0); A0 = fma2(aSp[1], Ps1, A0); A0 = fma2(aSp[2], Ps2, A0);
        A0 = fma2(aSp[3], Ps3, A0); A0 = fma2(aSp[4], Ps4, A0);
        uint64_t A1 = pk2(rc.z, rc.w);
        A1 = fma2(aSp[0], Ps2, A1); A1 = fma2(aSp[1], Ps3, A1); A1 = fma2(aSp[2], Ps4, A1);
        A1 = fma2(aSp[3], Qs3, A1); A1 = fma2(aSp[4], Qs4, A1);
        // u_{t-1}: u-tap + s-tap chains
        uint64_t CU0 = bBp;
        CU0 = fma2(bSp[0], Pu0, CU0); CU0 = fma2(bSp[1], Pu1, CU0); CU0 = fma2(bSp[2], Pu2, CU0);
        CU0 = fma2(bSp[3], Pu3, CU0); CU0 = fma2(bSp[4], Pu4, CU0);
        uint64_t CU1 = bBp;
        CU1 = fma2(bSp[0], Pu2, CU1); CU1 = fma2(bSp[1], Pu3, CU1); CU1 = fma2(bSp[2], Pu4, CU1);
        CU1 = fma2(bSp[3], Qu3, CU1); CU1 = fma2(bSp[4], Qu4, CU1);
        uint64_t CS0 = fma2(bXp[0], Ps0, Z64);
        CS0 = fma2(bXp[1], Ps1, CS0); CS0 = fma2(bXp[2], Ps2, CS0);
        CS0 = fma2(bXp[3], Ps3, CS0); CS0 = fma2(bXp[4], Ps4, CS0);
        uint64_t CS1 = fma2(bXp[0], Ps2, Z64);
        CS1 = fma2(bXp[1], Ps3, CS1); CS1 = fma2(bXp[2], Ps4, CS1);
        CS1 = fma2(bXp[3], Qs3, CS1); CS1 = fma2(bXp[4], Qs4, CS1);
        const uint64_t C0 = add2(CU0, CS0);
        const uint64_t C1 = add2(CU1, CS1);

        float a0, a1, a2, a3, c0, c1, c2, c3;
        upk2(A0, a0, a1); upk2(A1, a2, a3);
        upk2(C0, c0, c1); upk2(C1, c2, c3);
        if (edgeW) {
            if (!inD[0]) { a0 = 0.f; c0 = 0.f; }
            if (!inD[1]) { a1 = 0.f; c1 = 0.f; }
            if (!inD[2]) { a2 = 0.f; c2 = 0.f; }
            if (!inD[3]) { a3 = 0.f; c3 = 0.f; }
        }
        if (own)
            stage_store4(&sm->stage[(t - 1) & 31][stIdx], c0, c1, c2, c3);
        s0 = a0; s1 = a1; s2 = a2; s3 = a3;
        u0 = c0; u1 = c1; u2 = c2; u3 = c3;

        rc = *ld;                                  // prefetch row t+4

        if ((t & 15) == 0) {                       // warp-private output flush
            __syncwarp();
            flushw(stg, O, t - 16, w, lane, rank);
        }

        if (t == te) {                             // exchange epoch (every 24 ticks)
            te += 24;
            const int buf = eb; eb ^= 1;
            if (own) {
                *reinterpret_cast<float4*>(&sm->sEx[buf][exIdx]) = make_float4(s0, s1, s2, s3);
                *reinterpret_cast<float4*>(&sm->uEx[buf][exIdx]) = make_float4(u0, u1, u2, u3);
                if (pubR) {
                    dsm_store2(&sm->sEx[buf][exIdx - 256], rank + 1, s0, s1);
                    dsm_store2(&sm->sEx[buf][exIdx - 254], rank + 1, s2, s3);
                    dsm_store2(&sm->uEx[buf][exIdx - 256], rank + 1, u0, u1);
                    dsm_store2(&sm->uEx[buf][exIdx - 254], rank + 1, u2, u3);
                }
                if (pubL) {
                    dsm_store2(&sm->sEx[buf][exIdx + 256], rank - 1, s0, s1);
                    dsm_store2(&sm->sEx[buf][exIdx + 258], rank - 1, s2, s3);
                    dsm_store2(&sm->uEx[buf][exIdx + 256], rank - 1, u0, u1);
                    dsm_store2(&sm->uEx[buf][exIdx + 258], rank - 1, u2, u3);
                }
            }
            CLUSTER_ARRIVE();
            CLUSTER_WAIT();
            if (!own) {
                float4 sv = *reinterpret_cast<const float4*>(&sm->sEx[buf][exIdx]);
                float4 uv = *reinterpret_cast<const float4*>(&sm->uEx[buf][exIdx]);
                s0 = sv.x; s1 = sv.y; s2 = sv.z; s3 = sv.w;
                u0 = uv.x; u1 = uv.y; u2 = uv.z; u3 = uv.w;
            }
        }
    };

    // t = 2 .. 1021 in x4 groups, then 1022, 1023
    const float4* pf = rowp(6);
    #pragma unroll 1
    for (int t = 2; t <= TT - 6; t += 4) {
        body(t,     rr0, pf);
        body(t + 1, rr1, pf + RS / 4);
        body(t + 2, rr2, pf + 2 * (RS / 4));
        body(t + 3, rr3, pf + 3 * (RS / 4));
        pf += 4 * (RS / 4);
    }
    body(TT - 2, rr0, pf);                 // prefetches padded rows 1026/1027
    body(TT - 1, rr1, pf + RS / 4);

    // epilogue t = TT: u_{TT-1} (scalar path) + final flush
    {
        float sL2, sL1, sR0, sR1, uL2, uL1, uR0, uR1;
        HALO4(s0, s1, s2, s3, sL2, sL1, sR0, sR1);
        HALO4(u0, u1, u2, u3, uL2, uL1, uR0, uR1);
        float cu[4] = {bB, bB, bB, bB};
        conv4acc(cu, uL2, uL1, u0, u1, u2, u3, uR0, uR1, bS);
        float cs[4] = {0.f, 0.f, 0.f, 0.f};
        conv4acc(cs, sL2, sL1, s0, s1, s2, s3, sR0, sR1, bX);
        float c[4] = {cu[0] + cs[0], cu[1] + cs[1], cu[2] + cs[2], cu[3] + cs[3]};
        if (edgeW) {
            #pragma unroll
            for (int j = 0; j < 4; ++j) if (!inD[j]) c[j] = 0.f;
        }
        if (own)
            stage_store4(&sm->stage[31][stIdx], c[0], c[1], c[2], c[3]);
        __syncwarp();
        flushw(stg, O, TT - 16, w, lane, rank);
    }
}

// R[b][0][p] = pre_b + conv(pre taps, src[b][0]) ; R[b][t][p] = c_b + conv(c x-taps, src[b][t])
template <int COLTAPS, int PHASE>
__global__ void __launch_bounds__(256)
yprep(const float* __restrict__ srcparam,
      const float* __restrict__ pw, const float* __restrict__ pb,
      const float* __restrict__ cw, const float* __restrict__ cbias)
{
    const int r = blockIdx.x & (TT - 1);
    const int b = blockIdx.x >> 10;
    const float* src = (PHASE == 0 ? srcparam : (const float*)g_scr);
    const float* xr = src + ((size_t)b * TT + r) * NN;
    float* yr = g_R + ((size_t)b * TT + r) * NN;
    float tp[5], bias;
    #pragma unroll
    for (int k = 0; k < 5; ++k) {
        const int ti = COLTAPS ? (5 * k + 2) : (10 + k);
        tp[k] = (r == 0) ? pw[ti] : cw[25 + ti];
    }
    bias = (r == 0) ? pb[0] : cbias[0];
    const int p0 = threadIdx.x * 4;
    #pragma unroll
    for (int j = 0; j < 4; ++j) {
        const int p = p0 + j;
        float acc = bias;
        #pragma unroll
        for (int k = 0; k < 5; ++k) {
            const int q = p + k - 2;
            const float v = (q >= 0 && q < NN) ? __ldg(xr + q) : 0.f;
            acc = fmaf(tp[k], v, acc);
        }
        yr[p] = acc;
    }
}

extern "C" void kernel_launch(void* const* d_in, const int* in_sizes, int n_in,
                              void* d_out, int out_size)
{
    (void)in_sizes; (void)n_in; (void)out_size;
    const float* x   = (const float*)d_in[0];
    const float* p1w = (const float*)d_in[1];
    const float* p1b = (const float*)d_in[2];
    const float* p2w = (const float*)d_in[3];
    const float* p2b = (const float*)d_in[4];
    const float* p3w = (const float*)d_in[5];
    const float* p3b = (const float*)d_in[6];
    const float* p4w = (const float*)d_in[7];
    const float* p4b = (const float*)d_in[8];
    const float* c1w = (const float*)d_in[9];
    const float* c1b = (const float*)d_in[10];
    const float* c2w = (const float*)d_in[11];
    const float* c2b = (const float*)d_in[12];
    const float* c3w = (const float*)d_in[13];
    const float* c3b = (const float*)d_in[14];
    const float* c4w = (const float*)d_in[15];
    const float* c4b = (const float*)d_in[16];

    cudaFuncSetAttribute(scan_kernel<0, 0>, cudaFuncAttributeMaxDynamicSharedMemorySize, (int)sizeof(Smem));
    cudaFuncSetAttribute(scan_kernel<1, 1>, cudaFuncAttributeMaxDynamicSharedMemorySize, (int)sizeof(Smem));

    // phase A: R = pre1/c1-x conv of x rows; scan (row taps) -> g_scr
    yprep<0, 0><<<8 * TT, 256>>>(x, p1w, p1b, c1w, c1b);
    scan_kernel<0, 0><<<8 * CLC, NTH, sizeof(Smem)>>>(nullptr, p2w, p2b, c1w, c2w, c2b);
    // phase B: R = pre3/c3-x conv of scr rows; scan (col taps) -> out
    yprep<1, 1><<<8 * TT, 256>>>(nullptr, p3w, p3b, c3w, c3b);
    scan_kernel<1, 1><<<8 * CLC, NTH, sizeof(Smem)>>>((float*)d_out, p4w, p4b, c3w, c4w, c4b);
}

// round 16
// speedup vs baseline: 1.1363x; 1.1363x over previous
#include <cuda_runtime.h>
#include <cstdint>

// SCM_19061064860184 — R16: MIO-lean cluster scan. 4 warps/CTA (128 thr), warp
// owns 64 positions + 32-halo/side (window 128 = 4 slots/thread). Per-SM MIO
// ops/tick halved vs R15 (the measured bottleneck). Epoch + flush every 16 ticks.
// Cluster of 4 CTAs per batch, grid 32. PHASE-0 form: s_t = convS(s_{t-1}) + R[t].

#define NN 1024
#define TT 1024
#define NTH 128
#define CLC 4
#define OWNC 256
#define EXW2 320          // CTA exchange window: 256 own + 2*32 halo
#define SW 258            // stage row stride (258 % 32 == 2 -> conflict-free flush)
#define FULLM 0xffffffffu

struct alignas(16) Smem {
    float sEx[2][EXW2];
    float uEx[2][EXW2];
    float stage[16][SW];
};

__device__ __align__(16) float g_scr[8 * NN * TT];          // phase-A output
__device__ __align__(16) float g_R[8 * NN * TT + 4 * NN];   // precomputed R (+4 pad rows)

// ---------- packed f32x2 helpers ----------
__device__ __forceinline__ uint64_t pk2(float lo, float hi) {
    uint64_t r; asm("mov.b64 %0, {%1, %2};" : "=l"(r) : "f"(lo), "f"(hi)); return r;
}
__device__ __forceinline__ void upk2(uint64_t v, float& lo, float& hi) {
    asm("mov.b64 {%0, %1}, %2;" : "=f"(lo), "=f"(hi) : "l"(v));
}
__device__ __forceinline__ uint64_t fma2(uint64_t a, uint64_t b, uint64_t c) {
    uint64_t d; asm("fma.rn.f32x2 %0, %1, %2, %3;" : "=l"(d) : "l"(a), "l"(b), "l"(c)); return d;
}
__device__ __forceinline__ uint64_t add2(uint64_t a, uint64_t b) {
    uint64_t d; asm("add.rn.f32x2 %0, %1, %2;" : "=l"(d) : "l"(a), "l"(b)); return d;
}

// scalar 4-slot conv (same per-output tap order as packed path)
__device__ __forceinline__ void conv4acc(float o[4],
    float L2, float L1, float v0, float v1, float v2, float v3, float R0, float R1,
    const float tp[5])
{
    o[0] = fmaf(tp[0], L2, o[0]); o[0] = fmaf(tp[1], L1, o[0]); o[0] = fmaf(tp[2], v0, o[0]);
    o[0] = fmaf(tp[3], v1, o[0]); o[0] = fmaf(tp[4], v2, o[0]);
    o[1] = fmaf(tp[0], L1, o[1]); o[1] = fmaf(tp[1], v0, o[1]); o[1] = fmaf(tp[2], v1, o[1]);
    o[1] = fmaf(tp[3], v2, o[1]); o[1] = fmaf(tp[4], v3, o[1]);
    o[2] = fmaf(tp[0], v0, o[2]); o[2] = fmaf(tp[1], v1, o[2]); o[2] = fmaf(tp[2], v2, o[2]);
    o[2] = fmaf(tp[3], v3, o[2]); o[2] = fmaf(tp[4], R0, o[2]);
    o[3] = fmaf(tp[0], v1, o[3]); o[3] = fmaf(tp[1], v2, o[3]); o[3] = fmaf(tp[2], v3, o[3]);
    o[3] = fmaf(tp[3], R0, o[3]); o[3] = fmaf(tp[4], R1, o[3]);
}

#define HALO4(v0, v1, v2, v3, L2, L1, R0, R1) do { \
    L1 = __shfl_up_sync(FULLM, v3, 1);             \
    L2 = __shfl_up_sync(FULLM, v2, 1);             \
    R0 = __shfl_down_sync(FULLM, v0, 1);           \
    R1 = __shfl_down_sync(FULLM, v1, 1);           \
} while (0)

#define CLUSTER_ARRIVE() asm volatile("barrier.cluster.arrive.aligned;" ::: "memory")
#define CLUSTER_WAIT()   asm volatile("barrier.cluster.wait.aligned;"   ::: "memory")

__device__ __forceinline__ void dsm_store2(const float* lptr, int trank, float a, float b)
{
    uint32_t la = (uint32_t)__cvta_generic_to_shared(lptr);
    uint32_t ra;
    asm volatile("mapa.shared::cluster.u32 %0, %1, %2;" : "=r"(ra) : "r"(la), "r"(trank));
    asm volatile("st.shared::cluster.v2.f32 [%0], {%1, %2};"
                 :: "r"(ra), "f"(a), "f"(b) : "memory");
}

// stage store: two float2s (stage rows only 8B-aligned on odd rows, stride 258)
__device__ __forceinline__ void stage_store4(float* p, float a, float b, float c, float d)
{
    *reinterpret_cast<float2*>(p)     = make_float2(a, b);
    *reinterpret_cast<float2*>(p + 2) = make_float2(c, d);
}

// warp-private flush of 16 u-rows (i0..i0+15, i0 % 16 == 0) for warp w's 64 own
// positions; transposed + reversed; float4 gmem stores (4 lanes share a 64B segment).
__device__ __forceinline__ void flushw(const float (*stg)[SW], float* __restrict__ O,
                                       int i0, int w, int lane, int rank)
{
    const int q = lane & 3;
    const int r = lane >> 2;
    const int cb = NN - 4 - i0 - 4 * q;
    #pragma unroll
    for (int k = 0; k < 8; ++k) {
        const int oi = r + 8 * k;                     // own index 0..63
        const int sa = w * 64 + oi;                   // stage column
        float4 v;
        v.x = stg[(i0 + 4 * q + 3) & 15][sa];
        v.y = stg[(i0 + 4 * q + 2) & 15][sa];
        v.z = stg[(i0 + 4 * q + 1) & 15][sa];
        v.w = stg[(i0 + 4 * q + 0) & 15][sa];
        *reinterpret_cast<float4*>(O + (size_t)(rank * OWNC + w * 64 + oi) * NN + cb) = v;
    }
}

// PHASE 0: writes g_scr; PHASE 1: writes OUTparam. R always g_R.
template <int COLTAPS, int PHASE>
__global__ void __launch_bounds__(NTH, 1) __cluster_dims__(CLC, 1, 1)
scan_kernel(float* __restrict__ OUTparam,
            const float* __restrict__ preBw, const float* __restrict__ preBb,
            const float* __restrict__ cAw,
            const float* __restrict__ cBw, const float* __restrict__ cBb)
{
    extern __shared__ char raw[];
    Smem* sm = reinterpret_cast<Smem*>(raw);
    const int rank  = blockIdx.x & (CLC - 1);
    const int batch = blockIdx.x >> 2;
    const float* RIN = g_R + (size_t)batch * NN * TT;
    float* O = (PHASE == 0 ? g_scr : OUTparam) + (size_t)batch * NN * TT;

    const int tid = threadIdx.x, w = tid >> 5, lane = tid & 31;
#define TI(k) (COLTAPS ? (5 * (k) + 2) : (10 + (k)))
    float aS[5], bS[5], bX[5], pB[5];
    uint64_t aSp[5], bSp[5], bXp[5];
    #pragma unroll
    for (int k = 0; k < 5; ++k) {
        aS[k] = cAw[TI(k)];
        bS[k] = cBw[TI(k)];
        bX[k] = cBw[25 + TI(k)];
        pB[k] = preBw[TI(k)];
        aSp[k] = pk2(aS[k], aS[k]);
        bSp[k] = pk2(bS[k], bS[k]);
        bXp[k] = pk2(bX[k], bX[k]);
    }
    const float bB = cBb[0], pBb = preBb[0];
    const uint64_t bBp = pk2(bB, bB);
    const uint64_t Z64 = pk2(0.f, 0.f);
#undef TI

    // geometry: global warp wg owns [wg*64, wg*64+64); window = own +/- 32.
    const int wg = rank * 4 + w;                 // 0..15
    const int g0 = wg * 64 - 32 + 4 * lane;      // global coord of slot 0
    bool inD[4];
    #pragma unroll
    for (int j = 0; j < 4; ++j) inD[j] = (g0 + j >= 0) && (g0 + j < NN);
    const bool own = (lane >= 8 && lane < 24);   // window slots [32,96) = own 64
    const bool edgeW = (wg == 0) || (wg == CLC * 4 - 1);
    const int exIdx = w * 64 + 4 * lane;         // exchange index (CTA pos + 32)
    const int stIdx = exIdx - 32;                // CTA-local own position (own lanes)
    const bool pubL = (rank > 0) && (w == 0) && (lane >= 8 && lane < 16);
    const bool pubR = (rank < CLC - 1) && (w == 3) && (lane >= 16 && lane < 24);
    const int gr = g0 < 0 ? 0 : (g0 > NN - 4 ? NN - 4 : g0);   // float4-safe clamp
    const float (*stg)[SW] = sm->stage;

    // zero exchange buffers (domain-edge halo regions stay 0 = padding)
    {
        float* p0 = &sm->sEx[0][0];
        float* p1 = &sm->uEx[0][0];
        for (int i = tid; i < 2 * EXW2; i += NTH) { p0[i] = 0.f; p1[i] = 0.f; }
    }
    CLUSTER_ARRIVE();
    CLUSTER_WAIT();

    const int RS = NN;
    auto rowp = [&](int t) { return reinterpret_cast<const float4*>(RIN + (size_t)t * RS + gr); };
    float4 ra  = *rowp(0);
    float4 rb  = *rowp(1);
    float4 rr0 = *rowp(2);
    float4 rr1 = *rowp(3);
    float4 rr2 = *rowp(4);
    float4 rr3 = *rowp(5);

    float s0, s1, s2, s3, u0, u1, u2, u3;

    // t = 0: s_0 = R[0] masked
    s0 = inD[0] ? ra.x : 0.f;
    s1 = inD[1] ? ra.y : 0.f;
    s2 = inD[2] ? ra.z : 0.f;
    s3 = inD[3] ? ra.w : 0.f;

    // t = 1: s_1 = convS(s_0) + R[1] ; u_0 = preB(s_0)   (scalar path)
    {
        float L2, L1, R0, R1;
        HALO4(s0, s1, s2, s3, L2, L1, R0, R1);
        float a[4] = {rb.x, rb.y, rb.z, rb.w};
        conv4acc(a, L2, L1, s0, s1, s2, s3, R0, R1, aS);
        float c[4] = {pBb, pBb, pBb, pBb};
        conv4acc(c, L2, L1, s0, s1, s2, s3, R0, R1, pB);
        if (edgeW) {
            #pragma unroll
            for (int j = 0; j < 4; ++j) if (!inD[j]) { a[j] = 0.f; c[j] = 0.f; }
        }
        s0 = a[0]; s1 = a[1]; s2 = a[2]; s3 = a[3];
        u0 = c[0]; u1 = c[1]; u2 = c[2]; u3 = c[3];
        if (own)
            stage_store4(&sm->stage[0][stIdx], u0, u1, u2, u3);
    }

    int te = 16;     // epoch + flush every 16 ticks (decay 2*16 = 32 = halo, tight)
    int eb = 0;

    auto body = [&](int t, float4& rc, const float4* ld) {
        float sL2, sL1, sR0, sR1, uL2, uL1, uR0, uR1;
        HALO4(s0, s1, s2, s3, sL2, sL1, sR0, sR1);
        HALO4(u0, u1, u2, u3, uL2, uL1, uR0, uR1);

        // packed shifted windows (7 unique per array)
        const uint64_t Ps0 = pk2(sL2, sL1), Ps1 = pk2(sL1, s0), Ps2 = pk2(s0, s1),
                       Ps3 = pk2(s1, s2),  Ps4 = pk2(s2, s3),
                       Qs3 = pk2(s3, sR0), Qs4 = pk2(sR0, sR1);
        const uint64_t Pu0 = pk2(uL2, uL1), Pu1 = pk2(uL1, u0), Pu2 = pk2(u0, u1),
                       Pu3 = pk2(u1, u2),  Pu4 = pk2(u2, u3),
                       Qu3 = pk2(u3, uR0), Qu4 = pk2(uR0, uR1);

        // s_t (two pipes), accumulator starts at R
        uint64_t A0 = pk2(rc.x, rc.y);
        A0 = fma2(aSp[0], Ps0, A0); A0 = fma2(aSp[1], Ps1, A0); A0 = fma2(aSp[2], Ps2, A0);
        A0 = fma2(aSp[3], Ps3, A0); A0 = fma2(aSp[4], Ps4, A0);
        uint64_t A1 = pk2(rc.z, rc.w);
        A1 = fma2(aSp[0], Ps2, A1); A1 = fma2(aSp[1], Ps3, A1); A1 = fma2(aSp[2], Ps4, A1);
        A1 = fma2(aSp[3], Qs3, A1); A1 = fma2(aSp[4], Qs4, A1);
        // u_{t-1}: u-tap + s-tap chains
        uint64_t CU0 = bBp;
        CU0 = fma2(bSp[0], Pu0, CU0); CU0 = fma2(bSp[1], Pu1, CU0); CU0 = fma2(bSp[2], Pu2, CU0);
        CU0 = fma2(bSp[3], Pu3, CU0); CU0 = fma2(bSp[4], Pu4, CU0);
        uint64_t CU1 = bBp;
        CU1 = fma2(bSp[0], Pu2, CU1); CU1 = fma2(bSp[1], Pu3, CU1); CU1 = fma2(bSp[2], Pu4, CU1);
        CU1 = fma2(bSp[3], Qu3, CU1); CU1 = fma2(bSp[4], Qu4, CU1);
        uint64_t CS0 = fma2(bXp[0], Ps0, Z64);
        CS0 = fma2(bXp[1], Ps1, CS0); CS0 = fma2(bXp[2], Ps2, CS0);
        CS0 = fma2(bXp[3], Ps3, CS0); CS0 = fma2(bXp[4], Ps4, CS0);
        uint64_t CS1 = fma2(bXp[0], Ps2, Z64);
        CS1 = fma2(bXp[1], Ps3, CS1); CS1 = fma2(bXp[2], Ps4, CS1);
        CS1 = fma2(bXp[3], Qs3, CS1); CS1 = fma2(bXp[4], Qs4, CS1);
        const uint64_t C0 = add2(CU0, CS0);
        const uint64_t C1 = add2(CU1, CS1);

        float a0, a1, a2, a3, c0, c1, c2, c3;
        upk2(A0, a0, a1); upk2(A1, a2, a3);
        upk2(C0, c0, c1); upk2(C1, c2, c3);
        if (edgeW) {
            if (!inD[0]) { a0 = 0.f; c0 = 0.f; }
            if (!inD[1]) { a1 = 0.f; c1 = 0.f; }
            if (!inD[2]) { a2 = 0.f; c2 = 0.f; }
            if (!inD[3]) { a3 = 0.f; c3 = 0.f; }
        }
        if (own)
            stage_store4(&sm->stage[(t - 1) & 15][stIdx], c0, c1, c2, c3);
        s0 = a0; s1 = a1; s2 = a2; s3 = a3;
        u0 = c0; u1 = c1; u2 = c2; u3 = c3;

        rc = *ld;                                  // prefetch row t+4

        if (t == te) {                             // epoch: flush + exchange (every 16)
            te += 16;
            const int buf = eb; eb ^= 1;
            if (own) {
                *reinterpret_cast<float4*>(&sm->sEx[buf][exIdx]) = make_float4(s0, s1, s2, s3);
                *reinterpret_cast<float4*>(&sm->uEx[buf][exIdx]) = make_float4(u0, u1, u2, u3);
                if (pubR) {
                    dsm_store2(&sm->sEx[buf][exIdx - 256], rank + 1, s0, s1);
                    dsm_store2(&sm->sEx[buf][exIdx - 254], rank + 1, s2, s3);
                    dsm_store2(&sm->uEx[buf][exIdx - 256], rank + 1, u0, u1);
                    dsm_store2(&sm->uEx[buf][exIdx - 254], rank + 1, u2, u3);
                }
                if (pubL) {
                    dsm_store2(&sm->sEx[buf][exIdx + 256], rank - 1, s0, s1);
                    dsm_store2(&sm->sEx[buf][exIdx + 258], rank - 1, s2, s3);
                    dsm_store2(&sm->uEx[buf][exIdx + 256], rank - 1, u0, u1);
                    dsm_store2(&sm->uEx[buf][exIdx + 258], rank - 1, u2, u3);
                }
            }
            CLUSTER_ARRIVE();
            __syncwarp();
            flushw(stg, O, t - 16, w, lane, rank);  // overlap with cluster wait
            CLUSTER_WAIT();
            if (!own) {
                float4 sv = *reinterpret_cast<const float4*>(&sm->sEx[buf][exIdx]);
                float4 uv = *reinterpret_cast<const float4*>(&sm->uEx[buf][exIdx]);
                s0 = sv.x; s1 = sv.y; s2 = sv.z; s3 = sv.w;
                u0 = uv.x; u1 = uv.y; u2 = uv.z; u3 = uv.w;
            }
        }
    };

    // t = 2 .. 1021 in x4 groups, then 1022, 1023
    const float4* pf = rowp(6);
    #pragma unroll 1
    for (int t = 2; t <= TT - 6; t += 4) {
        body(t,     rr0, pf);
        body(t + 1, rr1, pf + RS / 4);
        body(t + 2, rr2, pf + 2 * (RS / 4));
        body(t + 3, rr3, pf + 3 * (RS / 4));
        pf += 4 * (RS / 4);
    }
    body(TT - 2, rr0, pf);                 // prefetches padded rows 1026/1027
    body(TT - 1, rr1, pf + RS / 4);

    // epilogue t = TT: u_{TT-1} (scalar path) + final flush
    {
        float sL2, sL1, sR0, sR1, uL2, uL1, uR0, uR1;
        HALO4(s0, s1, s2, s3, sL2, sL1, sR0, sR1);
        HALO4(u0, u1, u2, u3, uL2, uL1, uR0, uR1);
        float cu[4] = {bB, bB, bB, bB};
        conv4acc(cu, uL2, uL1, u0, u1, u2, u3, uR0, uR1, bS);
        float cs[4] = {0.f, 0.f, 0.f, 0.f};
        conv4acc(cs, sL2, sL1, s0, s1, s2, s3, sR0, sR1, bX);
        float c[4] = {cu[0] + cs[0], cu[1] + cs[1], cu[2] + cs[2], cu[3] + cs[3]};
        if (edgeW) {
            #pragma unroll
            for (int j = 0; j < 4; ++j) if (!inD[j]) c[j] = 0.f;
        }
        if (own)
            stage_store4(&sm->stage[15][stIdx], c[0], c[1], c[2], c[3]);
        __syncwarp();
        flushw(stg, O, TT - 16, w, lane, rank);
    }
}

// R[b][0][p] = pre_b + conv(pre taps, src[b][0]) ; R[b][t][p] = c_b + conv(c x-taps, src[b][t])
template <int COLTAPS, int PHASE>
__global__ void __launch_bounds__(256)
yprep(const float* __restrict__ srcparam,
      const float* __restrict__ pw, const float* __restrict__ pb,
      const float* __restrict__ cw, const float* __restrict__ cbias)
{
    const int r = blockIdx.x & (TT - 1);
    const int b = blockIdx.x >> 10;
    const float* src = (PHASE == 0 ? srcparam : (const float*)g_scr);
    const float* xr = src + ((size_t)b * TT + r) * NN;
    float* yr = g_R + ((size_t)b * TT + r) * NN;
    float tp[5], bias;
    #pragma unroll
    for (int k = 0; k < 5; ++k) {
        const int ti = COLTAPS ? (5 * k + 2) : (10 + k);
        tp[k] = (r == 0) ? pw[ti] : cw[25 + ti];
    }
    bias = (r == 0) ? pb[0] : cbias[0];
    const int p0 = threadIdx.x * 4;
    #pragma unroll
    for (int j = 0; j < 4; ++j) {
        const int p = p0 + j;
        float acc = bias;
        #pragma unroll
        for (int k = 0; k < 5; ++k) {
            const int q = p + k - 2;
            const float v = (q >= 0 && q < NN) ? __ldg(xr + q) : 0.f;
            acc = fmaf(tp[k], v, acc);
        }
        yr[p] = acc;
    }
}

extern "C" void kernel_launch(void* const* d_in, const int* in_sizes, int n_in,
                              void* d_out, int out_size)
{
    (void)in_sizes; (void)n_in; (void)out_size;
    const float* x   = (const float*)d_in[0];
    const float* p1w = (const float*)d_in[1];
    const float* p1b = (const float*)d_in[2];
    const float* p2w = (const float*)d_in[3];
    const float* p2b = (const float*)d_in[4];
    const float* p3w = (const float*)d_in[5];
    const float* p3b = (const float*)d_in[6];
    const float* p4w = (const float*)d_in[7];
    const float* p4b = (const float*)d_in[8];
    const float* c1w = (const float*)d_in[9];
    const float* c1b = (const float*)d_in[10];
    const float* c2w = (const float*)d_in[11];
    const float* c2b = (const float*)d_in[12];
    const float* c3w = (const float*)d_in[13];
    const float* c3b = (const float*)d_in[14];
    const float* c4w = (const float*)d_in[15];
    const float* c4b = (const float*)d_in[16];

    cudaFuncSetAttribute(scan_kernel<0, 0>, cudaFuncAttributeMaxDynamicSharedMemorySize, (int)sizeof(Smem));
    cudaFuncSetAttribute(scan_kernel<1, 1>, cudaFuncAttributeMaxDynamicSharedMemorySize, (int)sizeof(Smem));

    // phase A: R = pre1/c1-x conv of x rows; scan (row taps) -> g_scr
    yprep<0, 0><<<8 * TT, 256>>>(x, p1w, p1b, c1w, c1b);
    scan_kernel<0, 0><<<8 * CLC, NTH, sizeof(Smem)>>>(nullptr, p2w, p2b, c1w, c2w, c2b);
    // phase B: R = pre3/c3-x conv of scr rows; scan (col taps) -> out
    yprep<1, 1><<<8 * TT, 256>>>(nullptr, p3w, p3b, c3w, c3b);
    scan_kernel<1, 1><<<8 * CLC, NTH, sizeof(Smem)>>>((float*)d_out, p4w, p4b, c3w, c4w, c4b);
}